// round 8
// baseline (speedup 1.0000x reference)
#include <cuda_runtime.h>
#include <cstdint>
#include <cstring>
#include <cstdio>
#include <cstdlib>

#define WC 48
#define NCELL (48*48*48)
#define TFULL 96
#define TTRI 48
#define OS_A 117649
#define OS_X 2401
#define OS_Y 49
#define BT 64                      // cells (threads) per block
#define NB (NCELL / BT)            // 1728 blocks (single wave: ~13/SM resident)

// Per-triangle recipe: n = (c1 + d1*h1 + d0*g0) x (c2 + d2*h2 + d0*g0), g0 = -h0
struct TriR {
    float c1x, c1y, c1z, c2x, c2y, c2z;
    float g0x, g0y, g0z, h1x, h1y, h1z, h2x, h2y, h2z;
    uint32_t epk;                  // e0 | e1<<8 | e2<<16
};
struct Params {
    TriR r[TTRI];                  // read in-loop via uniform LDCU (const port)
    uint32_t slotpack[24];         // col-group g: byte k = slot of col 4g+k (0xFF unused)
};

__device__ float4 g_sm[NCELL];
__device__ int    g_ctr;           // zeroed by memset node each call

// ---------------------------------------------------------------------------
// Fused kernel: phase 1 = R5's k_field verbatim; spin barrier; phase 2 = pairs
// ---------------------------------------------------------------------------
__global__ __launch_bounds__(BT) void k_fused(
    const float* __restrict__ off, const float* __restrict__ topo,
    float* __restrict__ out, Params P)
{
    __shared__ float    st[BT][49];   // 48 gathered topology cols (+pad)
    __shared__ float    sd[BT][13];   // 12 edge displacements (+pad)
    __shared__ uint32_t ssl[24];      // slot map
    __shared__ float    red[2];

    const int tid   = threadIdx.x;
    const int cell0 = blockIdx.x * BT;

    if (tid < 24) ssl[tid] = P.slotpack[tid];
    if (cell0 == 0 && tid == 0) out[0] = 0.0f;   // ordered before our release-fence

    // ---- phase 1: per-cell field (identical to R5 k_field) ----
    const int c = cell0 + tid;
    const int z = c % WC, y = (c / WC) % WC, x = c / (WC * WC);
    const float* ob = off + x * OS_X + y * OS_Y + z;
    sd[tid][0]  = ob[0];
    sd[tid][1]  = ob[OS_Y];
    sd[tid][2]  = ob[1];
    sd[tid][3]  = ob[OS_Y + 1];
    sd[tid][4]  = ob[OS_A];
    sd[tid][5]  = ob[OS_A + OS_X];
    sd[tid][6]  = ob[OS_A + 1];
    sd[tid][7]  = ob[OS_A + OS_X + 1];
    sd[tid][8]  = ob[2*OS_A];
    sd[tid][9]  = ob[2*OS_A + OS_X];
    sd[tid][10] = ob[2*OS_A + OS_Y];
    sd[tid][11] = ob[2*OS_A + OS_X + OS_Y];

    __syncthreads();   // ssl visible

    const float4* t4 = reinterpret_cast<const float4*>(topo) + (size_t)cell0 * 24;
    #pragma unroll
    for (int it = 0; it < 24; ++it) {
        int i = tid + it * BT;           // [0, BT*24)
        float4 v = t4[i];
        int r = i / 24, g = i % 24;
        uint32_t sp = ssl[g];
        uint32_t s0 = sp & 0xffu, s1 = (sp >> 8) & 0xffu,
                 s2 = (sp >> 16) & 0xffu, s3 = sp >> 24;
        if (s0 != 0xffu) st[r][s0] = v.x;
        if (s1 != 0xffu) st[r][s1] = v.y;
        if (s2 != 0xffu) st[r][s2] = v.z;
        if (s3 != 0xffu) st[r][s3] = v.w;
    }

    __syncthreads();

    float s_ = 0.f, mx = 0.f, my = 0.f, mz = 0.f;
    const float* drow = sd[tid];
    const float* trow = st[tid];
    #pragma unroll 4
    for (int t = 0; t < TTRI; ++t) {
        const TriR& R = P.r[t];                 // uniform -> LDCU + UR operands
        uint32_t e = R.epk;
        float d0 = drow[e & 0xffu];
        float d1 = drow[(e >> 8) & 0xffu];
        float d2 = drow[(e >> 16) & 0xffu];
        float ax = fmaf(d1, R.h1x, fmaf(d0, R.g0x, R.c1x));
        float ay = fmaf(d1, R.h1y, fmaf(d0, R.g0y, R.c1y));
        float az = fmaf(d1, R.h1z, fmaf(d0, R.g0z, R.c1z));
        float bx = fmaf(d2, R.h2x, fmaf(d0, R.g0x, R.c2x));
        float by = fmaf(d2, R.h2y, fmaf(d0, R.g0y, R.c2y));
        float bz = fmaf(d2, R.h2z, fmaf(d0, R.g0z, R.c2z));
        float nx = fmaf(ay, bz, -az * by);
        float ny = fmaf(az, bx, -ax * bz);
        float nz = fmaf(ax, by, -ay * bx);
        float inv = rsqrtf(fmaf(nx, nx, fmaf(ny, ny, fmaf(nz, nz, 1e-8f))));
        float p = trow[t];                      // slot t == triangle t (sorted map)
        s_ += p;
        float w = p * inv;
        mx = fmaf(w, nx, mx); my = fmaf(w, ny, my); mz = fmaf(w, nz, mz);
    }
    g_sm[c] = make_float4(s_, mx, my, mz);

    // ---- device-wide barrier (all NB blocks resident in one wave) ----
    __threadfence();                   // release own g_sm write (and out=0 for blk 0)
    __syncthreads();
    if (tid == 0) {
        atomicAdd(&g_ctr, 1);
        while (*(volatile int*)&g_ctr < NB) __nanosleep(64);
    }
    __syncthreads();
    __threadfence();                   // acquire: see all g_sm writes

    // ---- phase 2: pair terms for this block's cells (self from registers) ----
    float acc = s_*s_ - mx*mx - my*my - mz*mz;          // inner
    if (x < WC-1) { float4 b = g_sm[c + WC*WC]; acc += s_*b.x - mx*b.y - my*b.z - mz*b.w; }
    if (y < WC-1) { float4 b = g_sm[c + WC];    acc += s_*b.x - mx*b.y - my*b.z - mz*b.w; }
    if (z < WC-1) { float4 b = g_sm[c + 1];     acc += s_*b.x - mx*b.y - my*b.z - mz*b.w; }
    acc *= 2.0f;
    #pragma unroll
    for (int o = 16; o > 0; o >>= 1) acc += __shfl_down_sync(0xffffffffu, acc, o);
    if ((tid & 31) == 0) red[tid >> 5] = acc;
    __syncthreads();
    if (tid == 0) atomicAdd(out, red[0] + red[1]);
}

// ---------------------------------------------------------------------------
// HOST: geometry + params
// ---------------------------------------------------------------------------
static const int EC[12][3] = {{0,0,0},{0,1,0},{0,0,1},{0,1,1},
                              {0,0,0},{1,0,0},{0,0,1},{1,0,1},
                              {0,0,0},{1,0,0},{0,1,0},{1,1,0}};
static const int EA[12] = {0,0,0,0,1,1,1,1,2,2,2,2};

static void make_params(const int tri[TTRI][3], const int cols[TTRI], Params* P)
{
    for (int t = 0; t < TTRI; ++t) {
        int e0 = tri[t][0], e1 = tri[t][1], e2 = tri[t][2];
        float b0[3], b1[3], b2[3];
        for (int k = 0; k < 3; ++k) {
            b0[k] = EC[e0][k] + (k == EA[e0] ? 0.5f : 0.f);
            b1[k] = EC[e1][k] + (k == EA[e1] ? 0.5f : 0.f);
            b2[k] = EC[e2][k] + (k == EA[e2] ? 0.5f : 0.f);
        }
        TriR& R = P->r[t];
        R.c1x = b1[0]-b0[0]; R.c1y = b1[1]-b0[1]; R.c1z = b1[2]-b0[2];
        R.c2x = b2[0]-b0[0]; R.c2y = b2[1]-b0[1]; R.c2z = b2[2]-b0[2];
        R.g0x = -(float)(EA[e0]==0); R.g0y = -(float)(EA[e0]==1); R.g0z = -(float)(EA[e0]==2);
        R.h1x = (float)(EA[e1]==0);  R.h1y = (float)(EA[e1]==1);  R.h1z = (float)(EA[e1]==2);
        R.h2x = (float)(EA[e2]==0);  R.h2y = (float)(EA[e2]==1);  R.h2z = (float)(EA[e2]==2);
        R.epk = (uint32_t)e0 | ((uint32_t)e1 << 8) | ((uint32_t)e2 << 16);
    }
    for (int g = 0; g < 24; ++g) {
        uint32_t sp = 0;
        for (int k = 0; k < 4; ++k) {
            int col = 4*g + k, slot = 0xFF;
            for (int s = 0; s < TTRI; ++s) if (cols[s] == col) { slot = s; break; }
            sp |= (uint32_t)slot << (8*k);
        }
        P->slotpack[g] = sp;
    }
}

// ---- ground-truth tables from in-container python/numpy (verified working) ----
static const char* PY_CMD =
    "python3 -c 'import numpy as np;r=np.random.default_rng(0);"
    "a=[r.choice(12,size=3,replace=False) for _ in range(48)];"
    "b=np.sort(r.choice(96,size=48,replace=False));"
    "print(\"TRI=\"+\",\".join(str(int(v)) for t in a for v in t));"
    "print(\"TT=\"+\",\".join(str(int(v)) for v in b))' 2>/dev/null";

static bool tables_from_python(int tri[TTRI][3], int cols[TTRI])
{
    FILE* f = popen(PY_CMD, "r");
    if (!f) return false;
    char l1[1200], l2[1200];
    bool ok = fgets(l1, sizeof l1, f) && fgets(l2, sizeof l2, f) &&
              !strncmp(l1, "TRI=", 4) && !strncmp(l2, "TT=", 3);
    pclose(f);
    if (!ok) return false;
    const char* p = l1 + 4;
    for (int t = 0; t < TTRI; ++t)
        for (int k = 0; k < 3; ++k) {
            char* end; long e = strtol(p, &end, 10);
            if (end == p || e < 0 || e > 11) return false;
            tri[t][k] = (int)e; p = end; if (*p == ',') ++p;
        }
    p = l2 + 3;
    long prev = -1;
    for (int k = 0; k < TTRI; ++k) {
        char* end; long v = strtol(p, &end, 10);
        if (end == p || v <= prev || v >= TFULL) return false;
        cols[k] = (int)v; prev = v; p = end; if (*p == ',') ++p;
    }
    return true;
}

// ---- fallback RNG (SeedSequence(0)+PCG64, Lemire draws everywhere) ----
static void tables_fallback(int tri[TTRI][3], int cols[TTRI])
{
    uint32_t hc = 0x43b0d7e5u;
    auto hashmix = [&hc](uint32_t v) { v ^= hc; hc *= 0x931e8875u; v *= hc; v ^= v >> 16; return v; };
    auto mixf = [](uint32_t a, uint32_t b) { uint32_t r = a*0xca01f9ddu - b*0x4973f715u; return r ^ (r >> 16); };
    uint32_t pool[4];
    for (int i = 0; i < 4; ++i) pool[i] = hashmix(0u);
    for (int s = 0; s < 4; ++s) for (int d2 = 0; d2 < 4; ++d2)
        if (s != d2) pool[d2] = mixf(pool[d2], hashmix(pool[s]));
    uint32_t hb = 0x8b51f9ddu, w[8];
    for (int i = 0; i < 8; ++i) {
        uint32_t v = pool[i % 4]; v ^= hb; hb *= 0x58f38dedu; v *= hb; v ^= v >> 16; w[i] = v;
    }
    uint64_t u64s[4];
    for (int k = 0; k < 4; ++k) u64s[k] = (uint64_t)w[2*k] | ((uint64_t)w[2*k+1] << 32);
    const __uint128_t MULT = ((__uint128_t)0x2360ed051fc65da4ULL << 64) | 0x4385df649fccf645ULL;
    __uint128_t inc = ((((__uint128_t)u64s[2] << 64) | u64s[3]) << 1) | 1;
    __uint128_t state = 0;
    state = state * MULT + inc;
    state += ((__uint128_t)u64s[0] << 64) | u64s[1];
    state = state * MULT + inc;
    bool has32 = false; uint32_t buf32 = 0;
    auto next32 = [&]() -> uint32_t {
        if (has32) { has32 = false; return buf32; }
        state = state * MULT + inc;
        uint64_t hi = (uint64_t)(state >> 64), lo = (uint64_t)state;
        unsigned rot = (unsigned)(hi >> 58);
        uint64_t v = hi ^ lo;
        uint64_t n = (v >> rot) | (v << ((64u - rot) & 63u));
        has32 = true; buf32 = (uint32_t)(n >> 32);
        return (uint32_t)n;
    };
    auto lemire = [&](uint32_t rng) -> uint32_t {
        if (rng == 0) return 0;
        uint32_t re = rng + 1u;
        uint64_t m = (uint64_t)next32() * re;
        uint32_t left = (uint32_t)m;
        if (left < re) {
            uint32_t thr = (0xFFFFFFFFu - rng) % re;
            while (left < thr) { m = (uint64_t)next32() * re; left = (uint32_t)m; }
        }
        return (uint32_t)(m >> 32);
    };
    auto choice = [&](int pop, int size, int64_t* out) {
        uint64_t ss = (uint64_t)(1.2 * (double)size), mask = ss;
        mask|=mask>>1; mask|=mask>>2; mask|=mask>>4; mask|=mask>>8; mask|=mask>>16; mask|=mask>>32;
        int set_size = (int)(mask + 1);
        uint64_t hs[128];
        for (int i = 0; i < set_size; ++i) hs[i] = ~0ULL;
        int k = 0;
        for (int j = pop - size; j < pop; ++j, ++k) {
            uint64_t val = lemire((uint32_t)j);
            uint64_t loc = val & mask;
            while (hs[loc] != ~0ULL && hs[loc] != val) loc = (loc + 1) & mask;
            if (hs[loc] == ~0ULL) { hs[loc] = val; out[k] = (int64_t)val; }
            else {
                loc = (uint64_t)j & mask;
                while (hs[loc] != ~0ULL) loc = (loc + 1) & mask;
                hs[loc] = (uint64_t)j; out[k] = j;
            }
        }
        for (int i = size - 1; i >= 1; --i) {
            uint32_t j = lemire((uint32_t)i);
            int64_t t = out[i]; out[i] = out[j]; out[j] = t;
        }
    };
    int64_t tmp[TTRI];
    for (int t = 0; t < TTRI; ++t) {
        choice(12, 3, tmp);
        tri[t][0] = (int)tmp[0]; tri[t][1] = (int)tmp[1]; tri[t][2] = (int)tmp[2];
    }
    choice(TFULL, TTRI, tmp);
    for (int i = 1; i < TTRI; ++i) {
        int64_t key = tmp[i]; int j = i - 1;
        while (j >= 0 && tmp[j] > key) { tmp[j+1] = tmp[j]; --j; }
        tmp[j+1] = key;
    }
    for (int k = 0; k < TTRI; ++k) cols[k] = (int)tmp[k];
}

// ---------------------------------------------------------------------------
extern "C" void kernel_launch(void* const* d_in, const int* in_sizes, int n_in,
                              void* d_out, int out_size)
{
    const float* d_offset = (const float*)d_in[0];
    const float* d_topo   = (const float*)d_in[1];
    float* out = (float*)d_out;

    int tri[TTRI][3], cols[TTRI];
    if (!tables_from_python(tri, cols)) {
        fprintf(stderr, "ATHENA: PYFAIL, using fallback RNG tables\n");
        tables_fallback(tri, cols);
    }
    static Params P;
    make_params(tri, cols, &P);

    void* ctr_addr = nullptr;
    cudaGetSymbolAddress(&ctr_addr, g_ctr);
    cudaMemsetAsync(ctr_addr, 0, sizeof(int));

    k_fused<<<NB, BT>>>(d_offset, d_topo, out, P);
}